// round 3
// baseline (speedup 1.0000x reference)
#include <cuda_runtime.h>
#include <cuda_bf16.h>
#include <math_constants.h>
#include <limits.h>

// Segment-max pooling with sorted segment ids (N rows x 32 ch -> M segments).
// One warp owns CHUNK consecutive rows; lane = channel.
// Boundary positions inside the chunk are precomputed as a 64-bit ballot mask
// (2 shfl_up + 2 ballot per chunk); the inner loop is LDG-batched (BATCH=16)
// and tests one uniform mask bit per row -- shfl only at actual flushes.
// A warp is responsible for a segment iff the segment's first row lies in its
// chunk; it extends past the chunk end via ballot-scanned id blocks, then does
// one plain store. Gaps between consecutive ids are empty segments -> 0.

#define CHUNK 64
#define BATCH 16

__global__ __launch_bounds__(256) void seg_max_kernel(
    const float* __restrict__ feat,
    const int*   __restrict__ ids,
    float*       __restrict__ out,
    int N, int M)
{
    const unsigned FULL = 0xFFFFFFFFu;
    const int lane = threadIdx.x & 31;
    const int warp = blockIdx.x * (blockDim.x >> 5) + (threadIdx.x >> 5);

    const long long r0 = (long long)warp * CHUNK;
    if (r0 >= N) return;
    const int nrows = (int)(((long long)N - r0 < CHUNK) ? (N - r0) : CHUNK);

    // Coalesced load of this chunk's segment ids (2 x 32 lanes).
    int id_lo = (lane < nrows)      ? ids[r0 + lane]      : 0;
    int id_hi = (32 + lane < nrows) ? ids[r0 + 32 + lane] : 0;

    // id of the row just before our chunk.
    const int prev_id = (r0 > 0) ? ids[r0 - 1] : -1;

    int   cur         = prev_id;
    bool  responsible = false;
    float m           = -CUDART_INF_F;

    const float* fptr = feat + r0 * 32 + lane;

    if (nrows == CHUNK) {
        // Boundary mask: bit i set iff ids[r0+i] != ids[r0+i-1].
        int pid_lo = __shfl_up_sync(FULL, id_lo, 1);
        if (lane == 0) pid_lo = prev_id;
        unsigned mlo = __ballot_sync(FULL, id_lo != pid_lo);

        int id31 = __shfl_sync(FULL, id_lo, 31);
        int pid_hi = __shfl_up_sync(FULL, id_hi, 1);
        if (lane == 0) pid_hi = id31;
        unsigned mhi = __ballot_sync(FULL, id_hi != pid_hi);

        const unsigned long long bmask =
            ((unsigned long long)mhi << 32) | (unsigned long long)mlo;

        #pragma unroll
        for (int base = 0; base < CHUNK; base += BATCH) {
            float v[BATCH];
            #pragma unroll
            for (int j = 0; j < BATCH; ++j)
                v[j] = fptr[(base + j) * 32];

            #pragma unroll
            for (int j = 0; j < BATCH; ++j) {
                const int i = base + j;
                if ((bmask >> i) & 1ull) {        // warp-uniform (ballot mask)
                    int nid = __shfl_sync(FULL, (i < 32) ? id_lo : id_hi, i & 31);
                    if (responsible) {
                        out[(long long)cur * 32 + lane] = m;
                        for (int g = cur + 1; g < nid; ++g)
                            out[(long long)g * 32 + lane] = 0.0f;
                    }
                    cur = nid;
                    m = -CUDART_INF_F;
                    responsible = true;
                }
                m = fmaxf(m, v[j]);
            }
        }
    } else {
        // Ragged last chunk: simple scalar path (one warp in the grid).
        for (int i = 0; i < nrows; ++i) {
            int id = __shfl_sync(FULL, (i < 32) ? id_lo : id_hi, i & 31);
            if (id != cur) {
                if (responsible) {
                    out[(long long)cur * 32 + lane] = m;
                    for (int g = cur + 1; g < id; ++g)
                        out[(long long)g * 32 + lane] = 0.0f;
                }
                cur = id;
                m = -CUDART_INF_F;
                responsible = true;
            }
            m = fmaxf(m, fptr[(long long)i * 32]);
        }
    }

    // Finish the last segment we own: it may continue past the chunk end.
    long long r = r0 + nrows;
    if (responsible) {
        while (r < N) {                       // uniform condition
            long long rl = r + lane;
            int idn = (rl < N) ? ids[rl] : (cur + 1);   // sentinel != cur
            unsigned diff = __ballot_sync(FULL, idn != cur);
            int k = diff ? (__ffs(diff) - 1) : 32;      // continuation rows
            for (int j = 0; j < k; ++j)                 // independent loads
                m = fmaxf(m, feat[(r + j) * 32 + lane]);
            r += k;
            if (k < 32) break;
        }
        out[(long long)cur * 32 + lane] = m;
        int next_id = (r < N) ? ids[r] : M;
        for (int g = cur + 1; g < next_id; ++g)
            out[(long long)g * 32 + lane] = 0.0f;
    }

    // Leading gap: segments before ids[0] are empty.
    if (r0 == 0) {
        int first = ids[0];
        for (int g = 0; g < first; ++g)
            out[(long long)g * 32 + lane] = 0.0f;
    }
}

extern "C" void kernel_launch(void* const* d_in, const int* in_sizes, int n_in,
                              void* d_out, int out_size) {
    const float* feat = (const float*)d_in[0];
    const int*   ids  = (const int*)d_in[1];
    float*       out  = (float*)d_out;

    const int N = in_sizes[1];
    const int M = out_size / 32;

    const int warps   = (N + CHUNK - 1) / CHUNK;
    const int threads = 256;
    const int blocks  = (warps * 32 + threads - 1) / threads;

    seg_max_kernel<<<blocks, threads>>>(feat, ids, out, N, M);
}